// round 11
// baseline (speedup 1.0000x reference)
#include <cuda_runtime.h>
#include <cstdint>

#define N_OBJ   8192
#define N_FLOOR 8192
#define STEPS   100

#define DT_F        0.01f
#define TWO_R       0.002f
#define EPS_F       1e-12f

#define NB          128           // blocks == resident CTAs (1/SM)
#define NT          1024
#define OBJ_PER_BLK (N_OBJ / NB)  // 64
#define HALF        4096          // floor points per smem tile
#define NSLICE      16
#define PAIRS_PER_SLICE (HALF / 2 / NSLICE)   // 128

// persistent scratch (zero/plain-store only; deterministic across replays)
__device__ float    g_mxy[N_OBJ];
__device__ unsigned g_mind2bits[STEPS];
__device__ unsigned g_arr = 0;   // monotone arrive counter
__device__ unsigned g_rel = 0;   // monotone release counter

// ---------------------------------------------------------------------------
// packed f32x2 helpers (sm_10x 2xFP32 datapath, PTX-only)
// ---------------------------------------------------------------------------
__device__ __forceinline__ unsigned long long pack2(float lo, float hi) {
    unsigned long long r;
    asm("mov.b64 %0, {%1, %2};" : "=l"(r) : "f"(lo), "f"(hi));
    return r;
}
__device__ __forceinline__ void unpack2(float& lo, float& hi, unsigned long long v) {
    asm("mov.b64 {%0, %1}, %2;" : "=f"(lo), "=f"(hi) : "l"(v));
}
__device__ __forceinline__ unsigned long long add2(unsigned long long a, unsigned long long b) {
    unsigned long long r;
    asm("add.rn.f32x2 %0, %1, %2;" : "=l"(r) : "l"(a), "l"(b));
    return r;
}
__device__ __forceinline__ unsigned long long mul2(unsigned long long a, unsigned long long b) {
    unsigned long long r;
    asm("mul.rn.f32x2 %0, %1, %2;" : "=l"(r) : "l"(a), "l"(b));
    return r;
}
__device__ __forceinline__ unsigned long long fma2(unsigned long long a, unsigned long long b,
                                                   unsigned long long c) {
    unsigned long long r;
    asm("fma.rn.f32x2 %0, %1, %2, %3;" : "=l"(r) : "l"(a), "l"(b), "l"(c));
    return r;
}

// ---------------------------------------------------------------------------
// software grid barrier: all NB blocks are co-resident (grid == NB, 1 CTA/SM)
// monotone epoch counters -> safe across multiple barriers AND graph replays
// ---------------------------------------------------------------------------
__device__ __forceinline__ void grid_barrier() {
    __syncthreads();
    if (threadIdx.x == 0) {
        const unsigned rel0 = *(volatile unsigned*)&g_rel;  // snapshot BEFORE arrive
        __threadfence();
        const unsigned old = atomicAdd(&g_arr, 1u);
        if ((old % NB) == NB - 1) {          // last arriver releases
            __threadfence();
            atomicAdd(&g_rel, 1u);
        }
        while (*(volatile unsigned*)&g_rel == rel0) { }
        __threadfence();
    }
    __syncthreads();
}

// ---------------------------------------------------------------------------
// The whole problem in one persistent kernel.
// ---------------------------------------------------------------------------
__global__ void __launch_bounds__(NT, 1) mega_kernel(
    const float* __restrict__ obj, const float* __restrict__ flr,
    float* __restrict__ out, int out_size)
{
    __shared__ unsigned long long sfx[HALF / 2];   // 16 KB: pack(-fx[2j],-fx[2j+1])
    __shared__ unsigned long long sfy[HALF / 2];   // 16 KB
    __shared__ float    s_partial[NSLICE][OBJ_PER_BLK];   // 4 KB
    __shared__ float    s_mxy[OBJ_PER_BLK];
    __shared__ unsigned s_wmin[32];
    __shared__ int      s_star_sh;
    __shared__ float    s_tznC, s_tzcC;

    const int tid   = threadIdx.x;
    const int obj0  = blockIdx.x * OBJ_PER_BLK;
    const int olane = tid & 63;           // object within block
    const int slice = tid >> 6;           // 0..15, constant within a warp
    const float GDT = -9.8f * DT_F;

    // ===================== Phase 1: minxy2 for 64 owned objects =====================
    const int myobj = obj0 + olane;
    const float ox = obj[myobj * 3 + 0];
    const float oy = obj[myobj * 3 + 1];
    const unsigned long long ox2 = pack2(ox, ox);
    const unsigned long long oy2 = pack2(oy, oy);

    float m0 = __int_as_float(0x7F7FFFFF);
    float m1 = __int_as_float(0x7F7FFFFF);

    #pragma unroll
    for (int tile = 0; tile < N_FLOOR / HALF; tile++) {
        __syncthreads();        // protect smem tile before overwrite
        const int fbase = tile * HALF;
        for (int j = tid; j < HALF / 2; j += NT) {
            const int p = fbase + 2 * j;
            sfx[j] = pack2(-flr[p * 3 + 0], -flr[p * 3 + 3]);
            sfy[j] = pack2(-flr[p * 3 + 1], -flr[p * 3 + 4]);
        }
        __syncthreads();

        const int jb = slice * PAIRS_PER_SLICE;
        #pragma unroll 8
        for (int j = 0; j < PAIRS_PER_SLICE; j++) {
            const unsigned long long fx = sfx[jb + j];      // broadcast LDS
            const unsigned long long fy = sfy[jb + j];
            const unsigned long long dx = add2(ox2, fx);    // ox - fx (2 lanes)
            const unsigned long long dy = add2(oy2, fy);    // oy - fy
            const unsigned long long sq = mul2(dx, dx);
            const unsigned long long d2 = fma2(dy, dy, sq);
            float lo, hi;
            unpack2(lo, hi, d2);
            m0 = fminf(m0, lo);
            m1 = fminf(m1, hi);
        }
    }
    s_partial[slice][olane] = fminf(m0, m1);
    __syncthreads();

    if (tid < OBJ_PER_BLK) {
        float m = s_partial[0][tid];
        #pragma unroll
        for (int c = 1; c < NSLICE; c++) m = fminf(m, s_partial[c][tid]);
        s_mxy[tid] = m;
        g_mxy[obj0 + tid] = m;     // plain store: block owns these objects
    }
    __threadfence();
    grid_barrier();

    // ===================== Phase 2: blocks 0..99 each do one step =====================
    if (blockIdx.x < STEPS) {
        const int s = blockIdx.x;
        // free-fall tz at step s (same fp recurrence as the serial sim)
        float vz = 0.0f, tz = 0.0f;
        for (int k = 0; k <= s; k++) {
            vz = vz + GDT;
            tz = tz + vz * DT_F;
        }

        unsigned lbits = 0x7F7FFFFFu;
        #pragma unroll
        for (int i = tid; i < N_OBJ; i += NT) {           // 8 iterations
            const float dz = obj[i * 3 + 2] + tz;
            const float d2 = fmaf(dz, dz, g_mxy[i]);
            lbits = min(lbits, (unsigned)__float_as_int(d2));   // d2 >= 0
        }
        lbits = __reduce_min_sync(0xFFFFFFFFu, lbits);
        if ((tid & 31) == 0) s_wmin[tid >> 5] = lbits;
        __syncthreads();
        if (tid < 32) {
            const unsigned v = __reduce_min_sync(0xFFFFFFFFu, s_wmin[tid]);
            if (tid == 0) g_mind2bits[s] = v;
        }
    }
    __threadfence();
    grid_barrier();

    // ===================== Phase 3: first contact step + outputs =====================
    if (tid == 0) s_star_sh = 0x7FFFFFFF;
    __syncthreads();

    if (tid < STEPS) {
        const float md  = __int_as_float((int)g_mind2bits[tid]);
        const float pen = TWO_R - sqrtf(md + EPS_F);
        if (pen > 0.0f) atomicMin_block(&s_star_sh, tid);
    }
    __syncthreads();

    const int sstar = s_star_sh;
    if (tid == 0 && sstar < STEPS) {
        float vz = 0.0f, tz = 0.0f;
        for (int k = 0; k <= sstar; k++) {
            vz = vz + GDT;
            tz = tz + vz * DT_F;
        }
        const float md  = __int_as_float((int)g_mind2bits[sstar]);
        const float pen = TWO_R - sqrtf(md + EPS_F);
        s_tznC = tz;
        s_tzcC = tz + pen;
    }
    __syncthreads();

    if (tid < OBJ_PER_BLK) {
        const int i = obj0 + tid;
        const float px = obj[i * 3 + 0];
        const float py = obj[i * 3 + 1];
        const float z  = obj[i * 3 + 2];

        bool  col = false;
        float pz  = z;
        if (sstar < STEPS) {
            const float dz = z + s_tznC;
            const float d2 = fmaf(dz, dz, s_mxy[tid]);
            const float pk = TWO_R - sqrtf(d2 + EPS_F);
            if (pk > 0.0f) { col = true; pz = z + s_tzcC; }
        }

        out[i * 3 + 0] = px;
        out[i * 3 + 1] = py;
        out[i * 3 + 2] = pz;
        if (out_size >= N_OBJ * 4)
            out[out_size - N_OBJ + i] = col ? 1.0f : 0.0f;
    }
}

// ---------------------------------------------------------------------------
extern "C" void kernel_launch(void* const* d_in, const int* in_sizes, int n_in,
                              void* d_out, int out_size)
{
    const float* obj = (const float*)d_in[0];   // [8192,3]
    const float* flr = (const float*)d_in[1];   // [8192,3]
    float* out = (float*)d_out;

    mega_kernel<<<NB, NT>>>(obj, flr, out, out_size);
}